// round 1
// baseline (speedup 1.0000x reference)
#include <cuda_runtime.h>

// Problem constants (fixed by the dataset)
constexpr int D      = 128;     // embed size
constexpr int H      = 256;     // hidden size
constexpr int NODES  = 8192;    // 2*B
constexpr int BP     = 4096;    // pairs
constexpr int T_EDG  = NODES * 32;
constexpr int K1     = 3 * D;   // 384 (concat [e|ne|nr])
constexpr int K2     = 2 * H;   // 512

// Scratch (static device allocations are allowed)
__device__ float g_A1[(size_t)NODES * K1];    // 12.6 MB
__device__ float g_node[(size_t)NODES * H];   // 8.4 MB
__device__ float g_W1[K1 * H];                // 384 KB
__device__ float g_b1[H];

// ---------------------------------------------------------------------------
// Kernel 0: build W1 = [Wt ; Wn] (rows 0..127 = Wt, 128..383 = Wn), b1 = bt+bn
// ---------------------------------------------------------------------------
__global__ void prep_w1(const float* __restrict__ Wt, const float* __restrict__ Wn,
                        const float* __restrict__ bt, const float* __restrict__ bn) {
    int i = blockIdx.x * blockDim.x + threadIdx.x;
    const int tot = K1 * H;
    const int wt_sz = D * H;
    if (i < wt_sz)       g_W1[i] = Wt[i];
    else if (i < tot)    g_W1[i] = Wn[i - wt_sz];
    if (i < H)           g_b1[i] = bt[i] + bn[i];
}

// ---------------------------------------------------------------------------
// Kernel 1: gather + segment mean.
// One CTA per node, 128 threads (one per embedding dim).
// Writes A1 row: [ E[ent] (128) | mean E[nbr_e] (128) | mean R[nbr_r] (128) ]
// ---------------------------------------------------------------------------
__global__ void gather_mean(const float* __restrict__ E, const float* __restrict__ R,
                            const int* __restrict__ ents,
                            const int* __restrict__ nent,
                            const int* __restrict__ nrel,
                            const int* __restrict__ offs) {
    const int i = blockIdx.x;       // node
    const int t = threadIdx.x;      // dim 0..127

    const int start = offs[i];
    const int end   = (i + 1 < NODES) ? offs[i + 1] : T_EDG;
    const int cnt   = end - start;

    float e  = E[(size_t)ents[i] * D + t];
    float se = 0.f, sr = 0.f;
    #pragma unroll 4
    for (int j = start; j < end; j++) {
        se += E[(size_t)nent[j] * D + t];
        sr += R[(size_t)nrel[j] * D + t];
    }
    const float inv = 1.0f / (float)(cnt > 0 ? cnt : 1);

    float* row = g_A1 + (size_t)i * K1;
    row[t]         = e;
    row[D + t]     = se * inv;
    row[2 * D + t] = sr * inv;
}

// ---------------------------------------------------------------------------
// Tiled SGEMM with fused bias + ReLU.
// C[M,N] = relu(A[M,K] @ B[K,N] + bias[N])   (all row-major)
// ---------------------------------------------------------------------------
template <int BM, int BN, int BK, int TM, int TN>
__global__ void sgemm_bias_relu(const float* __restrict__ A,
                                const float* __restrict__ B,
                                const float* __restrict__ bias,
                                float* __restrict__ C,
                                int M, int N, int K) {
    constexpr int THREADS = (BM / TM) * (BN / TN);
    __shared__ float As[BK][BM];
    __shared__ float Bs[BK][BN];

    const int tid  = threadIdx.x;
    const int bx   = blockIdx.x;   // N tile
    const int by   = blockIdx.y;   // M tile
    const int tcol = tid % (BN / TN);
    const int trow = tid / (BN / TN);

    constexpr int A_LOADS = (BM * BK) / (4 * THREADS);
    constexpr int B_LOADS = (BK * BN) / (4 * THREADS);

    const float* Aptr = A + (size_t)by * BM * K;
    const float* Bptr = B + (size_t)bx * BN;

    float acc[TM][TN];
    #pragma unroll
    for (int i = 0; i < TM; i++)
        #pragma unroll
        for (int j = 0; j < TN; j++) acc[i][j] = 0.f;

    for (int k0 = 0; k0 < K; k0 += BK) {
        // Load A tile [BM x BK], store transposed into As[BK][BM]
        #pragma unroll
        for (int l = 0; l < A_LOADS; l++) {
            int idx = tid + l * THREADS;
            int row = idx / (BK / 4);
            int kc  = (idx % (BK / 4)) * 4;
            float4 v = *(const float4*)(Aptr + (size_t)row * K + k0 + kc);
            As[kc + 0][row] = v.x;
            As[kc + 1][row] = v.y;
            As[kc + 2][row] = v.z;
            As[kc + 3][row] = v.w;
        }
        // Load B tile [BK x BN]
        #pragma unroll
        for (int l = 0; l < B_LOADS; l++) {
            int idx = tid + l * THREADS;
            int row = idx / (BN / 4);
            int col = (idx % (BN / 4)) * 4;
            *(float4*)(&Bs[row][col]) =
                *(const float4*)(Bptr + (size_t)(k0 + row) * N + col);
        }
        __syncthreads();

        #pragma unroll
        for (int k = 0; k < BK; k++) {
            float ra[TM], rb[TN];
            #pragma unroll
            for (int i = 0; i < TM; i += 4)
                *(float4*)(&ra[i]) = *(const float4*)(&As[k][trow * TM + i]);
            #pragma unroll
            for (int j = 0; j < TN; j += 4)
                *(float4*)(&rb[j]) = *(const float4*)(&Bs[k][tcol * TN + j]);
            #pragma unroll
            for (int i = 0; i < TM; i++)
                #pragma unroll
                for (int j = 0; j < TN; j++)
                    acc[i][j] += ra[i] * rb[j];
        }
        __syncthreads();
    }

    // Epilogue: bias + relu, vectorized stores
    #pragma unroll
    for (int i = 0; i < TM; i++) {
        const int r = by * BM + trow * TM + i;
        float* crow = C + (size_t)r * N;
        #pragma unroll
        for (int j = 0; j < TN; j += 4) {
            const int c = bx * BN + tcol * TN + j;
            float4 v;
            v.x = fmaxf(acc[i][j + 0] + bias[c + 0], 0.f);
            v.y = fmaxf(acc[i][j + 1] + bias[c + 1], 0.f);
            v.z = fmaxf(acc[i][j + 2] + bias[c + 2], 0.f);
            v.w = fmaxf(acc[i][j + 3] + bias[c + 3], 0.f);
            *(float4*)(crow + c) = v;
        }
    }
}

// ---------------------------------------------------------------------------
extern "C" void kernel_launch(void* const* d_in, const int* in_sizes, int n_in,
                              void* d_out, int out_size) {
    const float* E    = (const float*)d_in[0];
    const float* R    = (const float*)d_in[1];
    const float* Wt   = (const float*)d_in[2];
    const float* bt   = (const float*)d_in[3];
    const float* Wn   = (const float*)d_in[4];
    const float* bn   = (const float*)d_in[5];
    const float* Wr   = (const float*)d_in[6];
    const float* br   = (const float*)d_in[7];
    const int*   ents = (const int*)d_in[8];
    const int*   nent = (const int*)d_in[9];
    const int*   nrel = (const int*)d_in[10];
    const int*   offs = (const int*)d_in[11];
    float* out = (float*)d_out;

    float *A1, *node, *W1, *b1;
    cudaGetSymbolAddress((void**)&A1,   g_A1);
    cudaGetSymbolAddress((void**)&node, g_node);
    cudaGetSymbolAddress((void**)&W1,   g_W1);
    cudaGetSymbolAddress((void**)&b1,   g_b1);

    // 0) weight concat + bias fuse
    prep_w1<<<(K1 * H + 255) / 256, 256>>>(Wt, Wn, bt, bn);

    // 1) gather + segment mean  -> A1 [NODES, 384]
    gather_mean<<<NODES, D>>>(E, R, ents, nent, nrel, offs);

    // 2) node = relu(A1 @ W1 + b1)   [8192, 256]
    sgemm_bias_relu<128, 128, 16, 8, 8>
        <<<dim3(H / 128, NODES / 128), 256>>>(A1, W1, b1, node, NODES, H, K1);

    // 3) pair = relu(node.view(4096,512) @ Wr + br)  [4096, 256]
    sgemm_bias_relu<64, 128, 16, 8, 8>
        <<<dim3(H / 128, BP / 64), 128>>>(node, Wr, br, out, BP, H, K2);
}

// round 2
// speedup vs baseline: 1.6243x; 1.6243x over previous
#include <cuda_runtime.h>
#include <cstdint>

// Problem constants (fixed by the dataset)
constexpr int D      = 128;     // embed size
constexpr int H      = 256;     // hidden size
constexpr int NODES  = 8192;    // 2*B
constexpr int BP     = 4096;    // pairs
constexpr int T_EDG  = NODES * 32;
constexpr int K1     = 3 * D;   // 384 (concat [e|ne|nr])
constexpr int K2     = 2 * H;   // 512

// Scratch
__device__ float g_A1[(size_t)NODES * K1];    // 12.6 MB
__device__ float g_node[(size_t)NODES * H];   // 8.4 MB
__device__ float g_W1[K1 * H];                // 384 KB
__device__ float g_b1[H];

// ---------------------------------------------------------------------------
// Kernel 0: W1 = [Wt ; Wn], b1 = bt + bn
// ---------------------------------------------------------------------------
__global__ void prep_w1(const float* __restrict__ Wt, const float* __restrict__ Wn,
                        const float* __restrict__ bt, const float* __restrict__ bn) {
    int i = blockIdx.x * blockDim.x + threadIdx.x;
    const int tot = K1 * H;
    const int wt_sz = D * H;
    if (i < wt_sz)       g_W1[i] = Wt[i];
    else if (i < tot)    g_W1[i] = Wn[i - wt_sz];
    if (i < H)           g_b1[i] = bt[i] + bn[i];
}

// ---------------------------------------------------------------------------
// Kernel 1: gather + segment mean. 1 CTA/node, 128 threads (one per dim).
// ---------------------------------------------------------------------------
__global__ void gather_mean(const float* __restrict__ E, const float* __restrict__ R,
                            const int* __restrict__ ents,
                            const int* __restrict__ nent,
                            const int* __restrict__ nrel,
                            const int* __restrict__ offs) {
    const int i = blockIdx.x;
    const int t = threadIdx.x;

    const int start = offs[i];
    const int end   = (i + 1 < NODES) ? offs[i + 1] : T_EDG;
    const int cnt   = end - start;

    float e  = E[(size_t)ents[i] * D + t];
    float se = 0.f, sr = 0.f;
    #pragma unroll 4
    for (int j = start; j < end; j++) {
        se += E[(size_t)nent[j] * D + t];
        sr += R[(size_t)nrel[j] * D + t];
    }
    const float inv = 1.0f / (float)(cnt > 0 ? cnt : 1);

    float* row = g_A1 + (size_t)i * K1;
    row[t]         = e;
    row[D + t]     = se * inv;
    row[2 * D + t] = sr * inv;
}

// ---------------------------------------------------------------------------
// TF32 tensor-core GEMM with fused bias + ReLU.
// C[M,N] = relu(A[M,K] @ B[K,N] + bias[N]); A,B,C row-major, fp32 in/out.
// mma.sync.aligned.m16n8k8.row.col.f32.tf32.tf32.f32
// CTA tile BM x BN, BK=16 (two k8 steps), warp grid WM x WN,
// warp tile (BM/WM) x (BN/WN). Double-buffered smem, conflict-free strides.
// ---------------------------------------------------------------------------
__device__ __forceinline__ uint32_t f2tf32(float f) {
    uint32_t u;
    asm("cvt.rna.tf32.f32 %0, %1;" : "=r"(u) : "f"(f));
    return u;
}

template <int BM, int BN, int WM, int WN>
__global__ void __launch_bounds__(WM * WN * 32)
mma_gemm_bias_relu(const float* __restrict__ A, const float* __restrict__ B,
                   const float* __restrict__ bias, float* __restrict__ C,
                   int M, int N, int K) {
    constexpr int BK      = 16;
    constexpr int THREADS = WM * WN * 32;
    constexpr int TMW     = BM / WM;          // warp m-tile
    constexpr int TNW     = BN / WN;          // warp n-tile
    constexpr int MF      = TMW / 16;         // m16 frags per warp
    constexpr int NF      = TNW / 8;          // n8 frags per warp
    constexpr int SAS     = 20;               // A smem row stride (floats): 20*4 % 32banks -> conflict-free frag loads
    constexpr int SBS     = BN + 8;           // B smem row stride: mod 32 == 8 -> conflict-free frag loads
    constexpr int A_LD4   = (BM * BK) / (4 * THREADS);   // float4 loads per thread
    constexpr int B_LD4   = (BK * BN) / (4 * THREADS);

    __shared__ uint32_t sA[2][BM * SAS];
    __shared__ uint32_t sB[2][BK * SBS];

    const int tid  = threadIdx.x;
    const int wid  = tid >> 5;
    const int lane = tid & 31;
    const int grp  = lane >> 2;    // 0..7
    const int tg   = lane & 3;     // 0..3
    const int wm   = wid % WM;
    const int wn   = wid / WM;

    const int bx = blockIdx.x;     // N tile
    const int by = blockIdx.y;     // M tile

    const float* Ag = A + (size_t)by * BM * K;
    const float* Bg = B + (size_t)bx * BN;

    float acc[MF][NF][4];
    #pragma unroll
    for (int i = 0; i < MF; i++)
        #pragma unroll
        for (int j = 0; j < NF; j++)
            #pragma unroll
            for (int c = 0; c < 4; c++) acc[i][j][c] = 0.f;

    // --- tile loaders -------------------------------------------------------
    auto load_global = [&](int t, float4 (&pa)[A_LD4], float4 (&pb)[B_LD4]) {
        const int k0 = t * BK;
        #pragma unroll
        for (int l = 0; l < A_LD4; l++) {
            int idx = tid + l * THREADS;
            int row = idx >> 2;            // BK/4 = 4 float4 per row
            int c4  = idx & 3;
            pa[l] = *(const float4*)(Ag + (size_t)row * K + k0 + c4 * 4);
        }
        #pragma unroll
        for (int l = 0; l < B_LD4; l++) {
            int idx = tid + l * THREADS;
            int row = idx / (BN / 4);
            int c4  = idx % (BN / 4);
            pb[l] = *(const float4*)(Bg + (size_t)(k0 + row) * N + c4 * 4);
        }
    };
    auto store_smem = [&](int stg, const float4 (&pa)[A_LD4], const float4 (&pb)[B_LD4]) {
        #pragma unroll
        for (int l = 0; l < A_LD4; l++) {
            int idx = tid + l * THREADS;
            int row = idx >> 2;
            int c4  = idx & 3;
            uint32_t* p = &sA[stg][row * SAS + c4 * 4];
            p[0] = f2tf32(pa[l].x); p[1] = f2tf32(pa[l].y);
            p[2] = f2tf32(pa[l].z); p[3] = f2tf32(pa[l].w);
        }
        #pragma unroll
        for (int l = 0; l < B_LD4; l++) {
            int idx = tid + l * THREADS;
            int row = idx / (BN / 4);
            int c4  = idx % (BN / 4);
            uint32_t* p = &sB[stg][row * SBS + c4 * 4];
            p[0] = f2tf32(pb[l].x); p[1] = f2tf32(pb[l].y);
            p[2] = f2tf32(pb[l].z); p[3] = f2tf32(pb[l].w);
        }
    };

    // prologue: tile 0 -> stage 0
    {
        float4 pa[A_LD4]; float4 pb[B_LD4];
        load_global(0, pa, pb);
        store_smem(0, pa, pb);
    }
    __syncthreads();

    const int ntiles = K / BK;
    int cur = 0;

    for (int t = 0; t < ntiles; t++) {
        float4 pa[A_LD4]; float4 pb[B_LD4];
        const bool more = (t + 1 < ntiles);
        if (more) load_global(t + 1, pa, pb);

        // compute on stage cur: two k8 steps
        #pragma unroll
        for (int ks = 0; ks < BK; ks += 8) {
            uint32_t af[MF][4];
            #pragma unroll
            for (int i = 0; i < MF; i++) {
                int rb = wm * TMW + i * 16 + grp;
                af[i][0] = sA[cur][(rb + 0) * SAS + ks + tg];
                af[i][1] = sA[cur][(rb + 8) * SAS + ks + tg];
                af[i][2] = sA[cur][(rb + 0) * SAS + ks + tg + 4];
                af[i][3] = sA[cur][(rb + 8) * SAS + ks + tg + 4];
            }
            uint32_t bf[NF][2];
            #pragma unroll
            for (int j = 0; j < NF; j++) {
                int cb = wn * TNW + j * 8 + grp;
                bf[j][0] = sB[cur][(ks + tg)     * SBS + cb];
                bf[j][1] = sB[cur][(ks + tg + 4) * SBS + cb];
            }
            #pragma unroll
            for (int i = 0; i < MF; i++)
                #pragma unroll
                for (int j = 0; j < NF; j++) {
                    asm volatile(
                        "mma.sync.aligned.m16n8k8.row.col.f32.tf32.tf32.f32 "
                        "{%0,%1,%2,%3}, {%4,%5,%6,%7}, {%8,%9}, {%0,%1,%2,%3};"
                        : "+f"(acc[i][j][0]), "+f"(acc[i][j][1]),
                          "+f"(acc[i][j][2]), "+f"(acc[i][j][3])
                        : "r"(af[i][0]), "r"(af[i][1]), "r"(af[i][2]), "r"(af[i][3]),
                          "r"(bf[j][0]), "r"(bf[j][1]));
                }
        }

        if (more) store_smem(cur ^ 1, pa, pb);
        __syncthreads();
        cur ^= 1;
    }

    // epilogue: bias + relu
    #pragma unroll
    for (int i = 0; i < MF; i++) {
        const int r0 = by * BM + wm * TMW + i * 16 + grp;
        #pragma unroll
        for (int j = 0; j < NF; j++) {
            const int c = bx * BN + wn * TNW + j * 8 + tg * 2;
            const float b0 = bias[c], b1 = bias[c + 1];
            float2 v0, v1;
            v0.x = fmaxf(acc[i][j][0] + b0, 0.f);
            v0.y = fmaxf(acc[i][j][1] + b1, 0.f);
            v1.x = fmaxf(acc[i][j][2] + b0, 0.f);
            v1.y = fmaxf(acc[i][j][3] + b1, 0.f);
            *(float2*)(C + (size_t)r0 * N + c)       = v0;
            *(float2*)(C + (size_t)(r0 + 8) * N + c) = v1;
        }
    }
}

// ---------------------------------------------------------------------------
extern "C" void kernel_launch(void* const* d_in, const int* in_sizes, int n_in,
                              void* d_out, int out_size) {
    const float* E    = (const float*)d_in[0];
    const float* R    = (const float*)d_in[1];
    const float* Wt   = (const float*)d_in[2];
    const float* bt   = (const float*)d_in[3];
    const float* Wn   = (const float*)d_in[4];
    const float* bn   = (const float*)d_in[5];
    const float* Wr   = (const float*)d_in[6];
    const float* br   = (const float*)d_in[7];
    const int*   ents = (const int*)d_in[8];
    const int*   nent = (const int*)d_in[9];
    const int*   nrel = (const int*)d_in[10];
    const int*   offs = (const int*)d_in[11];
    float* out = (float*)d_out;

    float *A1, *node, *W1, *b1;
    cudaGetSymbolAddress((void**)&A1,   g_A1);
    cudaGetSymbolAddress((void**)&node, g_node);
    cudaGetSymbolAddress((void**)&W1,   g_W1);
    cudaGetSymbolAddress((void**)&b1,   g_b1);

    // 0) weight concat + bias fuse
    prep_w1<<<(K1 * H + 255) / 256, 256>>>(Wt, Wn, bt, bn);

    // 1) gather + segment mean  -> A1 [8192, 384]
    gather_mean<<<NODES, D>>>(E, R, ents, nent, nrel, offs);

    // 2) node = relu(A1 @ W1 + b1)   [8192, 256]
    //    128x128 CTA tile, 8 warps (4x2), warp tile 32x64 -> grid 2 x 64 = 128 CTAs
    mma_gemm_bias_relu<128, 128, 4, 2>
        <<<dim3(H / 128, NODES / 128), 256>>>(A1, W1, b1, node, NODES, H, K1);

    // 3) pair = relu(node.view(4096,512) @ Wr + br)  [4096, 256]
    //    128x64 CTA tile, 8 warps (4x2), warp tile 32x32 -> grid 4 x 32 = 128 CTAs
    mma_gemm_bias_relu<128, 64, 4, 2>
        <<<dim3(H / 64, BP / 128), 256>>>(node, Wr, br, out, BP, H, K2);
}

// round 3
// speedup vs baseline: 1.9253x; 1.1853x over previous
#include <cuda_runtime.h>
#include <cstdint>

// Problem constants (fixed by the dataset)
constexpr int D      = 128;     // embed size
constexpr int H      = 256;     // hidden size
constexpr int NODES  = 8192;    // 2*B
constexpr int BP     = 4096;    // pairs
constexpr int T_EDG  = NODES * 32;
constexpr int K1     = 3 * D;   // 384
constexpr int K2     = 2 * H;   // 512

// Scratch (all GEMM inputs stored pre-converted to tf32-in-fp32 container)
__device__ float g_A1[(size_t)NODES * K1];
__device__ float g_node[(size_t)NODES * H];
__device__ float g_W1[K1 * H];
__device__ float g_Wr[K2 * H];
__device__ float g_b1[H];

__device__ __forceinline__ uint32_t f2tf32(float f) {
    uint32_t u;
    asm("cvt.rna.tf32.f32 %0, %1;" : "=r"(u) : "f"(f));
    return u;
}
__device__ __forceinline__ float cvt_tf32(float f) {
    return __uint_as_float(f2tf32(f));
}

// ---------------------------------------------------------------------------
// Kernel 0: W1 = tf32([Wt ; Wn]), Wr_tf32, b1 = bt + bn
// ---------------------------------------------------------------------------
__global__ void prep_w(const float* __restrict__ Wt, const float* __restrict__ Wn,
                       const float* __restrict__ bt, const float* __restrict__ bn,
                       const float* __restrict__ Wr) {
    int i = blockIdx.x * blockDim.x + threadIdx.x;
    const int wt_sz = D * H;
    if (i < wt_sz)          g_W1[i] = cvt_tf32(Wt[i]);
    else if (i < K1 * H)    g_W1[i] = cvt_tf32(Wn[i - wt_sz]);
    if (i < K2 * H)         g_Wr[i] = cvt_tf32(Wr[i]);
    if (i < H)              g_b1[i] = bt[i] + bn[i];
}

// ---------------------------------------------------------------------------
// Kernel 1: gather + segment mean. One WARP per node; lane = 4 dims (float4).
// Indices preloaded coalesced, broadcast via shfl. Output tf32-converted.
// ---------------------------------------------------------------------------
__global__ void gather_mean(const float* __restrict__ E, const float* __restrict__ R,
                            const int* __restrict__ ents,
                            const int* __restrict__ nent,
                            const int* __restrict__ nrel,
                            const int* __restrict__ offs) {
    const int gw   = (blockIdx.x * blockDim.x + threadIdx.x) >> 5;  // node
    const int lane = threadIdx.x & 31;
    if (gw >= NODES) return;

    const int start = offs[gw];
    const int end   = (gw + 1 < NODES) ? offs[gw + 1] : T_EDG;
    const int cnt   = end - start;

    const float4* E4 = (const float4*)E;
    const float4* R4 = (const float4*)R;

    float4 se = make_float4(0.f, 0.f, 0.f, 0.f);
    float4 sr = make_float4(0.f, 0.f, 0.f, 0.f);

    for (int base = start; base < end; base += 32) {
        const int rem = end - base;
        const int n   = rem < 32 ? rem : 32;
        const int iE  = (lane < rem) ? nent[base + lane] : 0;
        const int iR  = (lane < rem) ? nrel[base + lane] : 0;
        #pragma unroll 4
        for (int j = 0; j < n; j++) {
            const int ie = __shfl_sync(0xffffffffu, iE, j);
            const int ir = __shfl_sync(0xffffffffu, iR, j);
            float4 ve = E4[(size_t)ie * (D / 4) + lane];
            float4 vr = R4[(size_t)ir * (D / 4) + lane];
            se.x += ve.x; se.y += ve.y; se.z += ve.z; se.w += ve.w;
            sr.x += vr.x; sr.y += vr.y; sr.z += vr.z; sr.w += vr.w;
        }
    }
    const float inv = 1.0f / (float)(cnt > 0 ? cnt : 1);
    float4 e = E4[(size_t)ents[gw] * (D / 4) + lane];

    float* row = g_A1 + (size_t)gw * K1;
    float4 o0, o1, o2;
    o0.x = cvt_tf32(e.x);        o0.y = cvt_tf32(e.y);
    o0.z = cvt_tf32(e.z);        o0.w = cvt_tf32(e.w);
    o1.x = cvt_tf32(se.x * inv); o1.y = cvt_tf32(se.y * inv);
    o1.z = cvt_tf32(se.z * inv); o1.w = cvt_tf32(se.w * inv);
    o2.x = cvt_tf32(sr.x * inv); o2.y = cvt_tf32(sr.y * inv);
    o2.z = cvt_tf32(sr.z * inv); o2.w = cvt_tf32(sr.w * inv);
    *(float4*)(row + lane * 4)         = o0;
    *(float4*)(row + D + lane * 4)     = o1;
    *(float4*)(row + 2 * D + lane * 4) = o2;
}

// ---------------------------------------------------------------------------
// cp.async helper
// ---------------------------------------------------------------------------
__device__ __forceinline__ void cp16(void* smem, const void* gmem) {
    uint32_t s = (uint32_t)__cvta_generic_to_shared(smem);
    asm volatile("cp.async.cg.shared.global [%0], [%1], 16;" :: "r"(s), "l"(gmem));
}

// ---------------------------------------------------------------------------
// TF32 tensor-core GEMM, 3-stage cp.async pipeline, fused bias+ReLU.
// Inputs A,B already tf32-rounded. If CVT_OUT, output stored tf32-rounded.
// C[M,N] = relu(A[M,K] @ B[K,N] + bias[N])
// ---------------------------------------------------------------------------
template <int BM, int BN, int WM, int WN, bool CVT_OUT>
__global__ void __launch_bounds__(WM * WN * 32)
mma_gemm_bias_relu(const float* __restrict__ A, const float* __restrict__ B,
                   const float* __restrict__ bias, float* __restrict__ C,
                   int M, int N, int K) {
    constexpr int BK      = 16;
    constexpr int STAGES  = 3;
    constexpr int THREADS = WM * WN * 32;
    constexpr int TMW     = BM / WM;
    constexpr int TNW     = BN / WN;
    constexpr int MF      = TMW / 16;
    constexpr int NF      = TNW / 8;
    constexpr int SAS     = BK + 4;          // 20 floats: conflict-free frag loads
    constexpr int SBS     = BN + 8;          // mod 32 == 8: conflict-free frag loads
    constexpr int A_CH    = (BM * (BK / 4)) / THREADS;   // 16B chunks per thread
    constexpr int B_CH    = (BK * (BN / 4)) / THREADS;

    __shared__ float sA[STAGES][BM * SAS];
    __shared__ float sB[STAGES][BK * SBS];

    const int tid  = threadIdx.x;
    const int wid  = tid >> 5;
    const int lane = tid & 31;
    const int grp  = lane >> 2;
    const int tg   = lane & 3;
    const int wm   = wid % WM;
    const int wn   = wid / WM;

    const int bx = blockIdx.x;
    const int by = blockIdx.y;

    const float* Ag = A + (size_t)by * BM * K;
    const float* Bg = B + (size_t)bx * BN;

    float acc[MF][NF][4];
    #pragma unroll
    for (int i = 0; i < MF; i++)
        #pragma unroll
        for (int j = 0; j < NF; j++)
            #pragma unroll
            for (int c = 0; c < 4; c++) acc[i][j][c] = 0.f;

    auto issue = [&](int t, int stg) {
        const float* At = Ag + t * BK;
        #pragma unroll
        for (int l = 0; l < A_CH; l++) {
            int idx = tid + l * THREADS;
            int row = idx >> 2;
            int c4  = idx & 3;
            cp16(&sA[stg][row * SAS + c4 * 4], At + (size_t)row * K + c4 * 4);
        }
        const float* Bt = Bg + (size_t)t * BK * N;
        #pragma unroll
        for (int l = 0; l < B_CH; l++) {
            int idx = tid + l * THREADS;
            int row = idx / (BN / 4);
            int c4  = idx % (BN / 4);
            cp16(&sB[stg][row * SBS + c4 * 4], Bt + (size_t)row * N + c4 * 4);
        }
    };

    const int ntiles = K / BK;

    #pragma unroll
    for (int s = 0; s < STAGES - 1; s++) {
        if (s < ntiles) issue(s, s);
        asm volatile("cp.async.commit_group;");
    }

    for (int t = 0; t < ntiles; t++) {
        asm volatile("cp.async.wait_group %0;" :: "n"(STAGES - 2));
        __syncthreads();

        const int nt = t + STAGES - 1;
        if (nt < ntiles) issue(nt, nt % STAGES);
        asm volatile("cp.async.commit_group;");

        const int stg = t % STAGES;
        #pragma unroll
        for (int ks = 0; ks < BK; ks += 8) {
            uint32_t af[MF][4];
            #pragma unroll
            for (int i = 0; i < MF; i++) {
                int rb = wm * TMW + i * 16 + grp;
                af[i][0] = __float_as_uint(sA[stg][(rb + 0) * SAS + ks + tg]);
                af[i][1] = __float_as_uint(sA[stg][(rb + 8) * SAS + ks + tg]);
                af[i][2] = __float_as_uint(sA[stg][(rb + 0) * SAS + ks + tg + 4]);
                af[i][3] = __float_as_uint(sA[stg][(rb + 8) * SAS + ks + tg + 4]);
            }
            uint32_t bf[NF][2];
            #pragma unroll
            for (int j = 0; j < NF; j++) {
                int cb = wn * TNW + j * 8 + grp;
                bf[j][0] = __float_as_uint(sB[stg][(ks + tg) * SBS + cb]);
                bf[j][1] = __float_as_uint(sB[stg][(ks + tg + 4) * SBS + cb]);
            }
            #pragma unroll
            for (int i = 0; i < MF; i++)
                #pragma unroll
                for (int j = 0; j < NF; j++) {
                    asm volatile(
                        "mma.sync.aligned.m16n8k8.row.col.f32.tf32.tf32.f32 "
                        "{%0,%1,%2,%3}, {%4,%5,%6,%7}, {%8,%9}, {%0,%1,%2,%3};"
                        : "+f"(acc[i][j][0]), "+f"(acc[i][j][1]),
                          "+f"(acc[i][j][2]), "+f"(acc[i][j][3])
                        : "r"(af[i][0]), "r"(af[i][1]), "r"(af[i][2]), "r"(af[i][3]),
                          "r"(bf[j][0]), "r"(bf[j][1]));
                }
        }
        __syncthreads();
    }

    // epilogue: bias + relu (+ optional tf32 rounding for the next GEMM)
    #pragma unroll
    for (int i = 0; i < MF; i++) {
        const int r0 = by * BM + wm * TMW + i * 16 + grp;
        #pragma unroll
        for (int j = 0; j < NF; j++) {
            const int c = bx * BN + wn * TNW + j * 8 + tg * 2;
            const float b0 = bias[c], b1 = bias[c + 1];
            float2 v0, v1;
            v0.x = fmaxf(acc[i][j][0] + b0, 0.f);
            v0.y = fmaxf(acc[i][j][1] + b1, 0.f);
            v1.x = fmaxf(acc[i][j][2] + b0, 0.f);
            v1.y = fmaxf(acc[i][j][3] + b1, 0.f);
            if (CVT_OUT) {
                v0.x = cvt_tf32(v0.x); v0.y = cvt_tf32(v0.y);
                v1.x = cvt_tf32(v1.x); v1.y = cvt_tf32(v1.y);
            }
            *(float2*)(C + (size_t)r0 * N + c)       = v0;
            *(float2*)(C + (size_t)(r0 + 8) * N + c) = v1;
        }
    }
}

// ---------------------------------------------------------------------------
extern "C" void kernel_launch(void* const* d_in, const int* in_sizes, int n_in,
                              void* d_out, int out_size) {
    const float* E    = (const float*)d_in[0];
    const float* R    = (const float*)d_in[1];
    const float* Wt   = (const float*)d_in[2];
    const float* bt   = (const float*)d_in[3];
    const float* Wn   = (const float*)d_in[4];
    const float* bn   = (const float*)d_in[5];
    const float* Wr   = (const float*)d_in[6];
    const float* br   = (const float*)d_in[7];
    const int*   ents = (const int*)d_in[8];
    const int*   nent = (const int*)d_in[9];
    const int*   nrel = (const int*)d_in[10];
    const int*   offs = (const int*)d_in[11];
    float* out = (float*)d_out;

    float *A1, *node, *W1, *Wr32, *b1;
    cudaGetSymbolAddress((void**)&A1,   g_A1);
    cudaGetSymbolAddress((void**)&node, g_node);
    cudaGetSymbolAddress((void**)&W1,   g_W1);
    cudaGetSymbolAddress((void**)&Wr32, g_Wr);
    cudaGetSymbolAddress((void**)&b1,   g_b1);

    // 0) weight prep (concat + tf32 conversion + bias fuse)
    prep_w<<<(K2 * H + 255) / 256, 256>>>(Wt, Wn, bt, bn, Wr);

    // 1) gather + segment mean -> A1 [8192, 384] (tf32)
    gather_mean<<<NODES / 8, 256>>>(E, R, ents, nent, nrel, offs);

    // 2) node = tf32(relu(A1 @ W1 + b1))   [8192, 256]
    mma_gemm_bias_relu<128, 128, 4, 2, true>
        <<<dim3(H / 128, NODES / 128), 256>>>(A1, W1, b1, node, NODES, H, K1);

    // 3) out = relu(node.view(4096,512) @ Wr + br)  [4096, 256]
    mma_gemm_bias_relu<128, 64, 4, 2, false>
        <<<dim3(H / 64, BP / 128), 256>>>(node, Wr32, br, out, BP, H, K2);
}

// round 4
// speedup vs baseline: 2.1270x; 1.1048x over previous
#include <cuda_runtime.h>
#include <cstdint>

// Problem constants (fixed by the dataset)
constexpr int D      = 128;     // embed size
constexpr int H      = 256;     // hidden size
constexpr int NODES  = 8192;    // 2*B
constexpr int BP     = 4096;    // pairs
constexpr int T_EDG  = NODES * 32;
constexpr int K1     = 3 * D;   // 384
constexpr int K2     = 2 * H;   // 512

// Scratch (all GEMM inputs stored pre-converted to tf32-in-fp32 container)
__device__ float g_A1[(size_t)NODES * K1];
__device__ float g_node[(size_t)NODES * H];
__device__ float g_W1[K1 * H];
__device__ float g_Wr[K2 * H];
__device__ float g_b1[H];

__device__ __forceinline__ uint32_t f2tf32(float f) {
    uint32_t u;
    asm("cvt.rna.tf32.f32 %0, %1;" : "=r"(u) : "f"(f));
    return u;
}
__device__ __forceinline__ float cvt_tf32(float f) {
    return __uint_as_float(f2tf32(f));
}

// ---------------------------------------------------------------------------
// Kernel 0: W1 = tf32([Wt ; Wn]), Wr_tf32, b1 = bt + bn
// ---------------------------------------------------------------------------
__global__ void prep_w(const float* __restrict__ Wt, const float* __restrict__ Wn,
                       const float* __restrict__ bt, const float* __restrict__ bn,
                       const float* __restrict__ Wr) {
    int i = blockIdx.x * blockDim.x + threadIdx.x;
    const int wt_sz = D * H;
    if (i < wt_sz)          g_W1[i] = cvt_tf32(Wt[i]);
    else if (i < K1 * H)    g_W1[i] = cvt_tf32(Wn[i - wt_sz]);
    if (i < K2 * H)         g_Wr[i] = cvt_tf32(Wr[i]);
    if (i < H)              g_b1[i] = bt[i] + bn[i];
}

// ---------------------------------------------------------------------------
// Kernel 1: gather + segment mean. One WARP per node; lane = 4 dims (float4).
// ---------------------------------------------------------------------------
__global__ void gather_mean(const float* __restrict__ E, const float* __restrict__ R,
                            const int* __restrict__ ents,
                            const int* __restrict__ nent,
                            const int* __restrict__ nrel,
                            const int* __restrict__ offs) {
    const int gw   = (blockIdx.x * blockDim.x + threadIdx.x) >> 5;  // node
    const int lane = threadIdx.x & 31;
    if (gw >= NODES) return;

    const int start = offs[gw];
    const int end   = (gw + 1 < NODES) ? offs[gw + 1] : T_EDG;
    const int cnt   = end - start;

    const float4* E4 = (const float4*)E;
    const float4* R4 = (const float4*)R;

    float4 se = make_float4(0.f, 0.f, 0.f, 0.f);
    float4 sr = make_float4(0.f, 0.f, 0.f, 0.f);

    if (cnt == 32) {
        // fast path: full warp of edges, fully unrolled broadcast
        const int iE = nent[start + lane];
        const int iR = nrel[start + lane];
        #pragma unroll 8
        for (int j = 0; j < 32; j++) {
            const int ie = __shfl_sync(0xffffffffu, iE, j);
            const int ir = __shfl_sync(0xffffffffu, iR, j);
            float4 ve = __ldg(&E4[(size_t)ie * (D / 4) + lane]);
            float4 vr = __ldg(&R4[(size_t)ir * (D / 4) + lane]);
            se.x += ve.x; se.y += ve.y; se.z += ve.z; se.w += ve.w;
            sr.x += vr.x; sr.y += vr.y; sr.z += vr.z; sr.w += vr.w;
        }
    } else {
        for (int base = start; base < end; base += 32) {
            const int rem = end - base;
            const int n   = rem < 32 ? rem : 32;
            const int iE  = (lane < rem) ? nent[base + lane] : 0;
            const int iR  = (lane < rem) ? nrel[base + lane] : 0;
            #pragma unroll 4
            for (int j = 0; j < n; j++) {
                const int ie = __shfl_sync(0xffffffffu, iE, j);
                const int ir = __shfl_sync(0xffffffffu, iR, j);
                float4 ve = __ldg(&E4[(size_t)ie * (D / 4) + lane]);
                float4 vr = __ldg(&R4[(size_t)ir * (D / 4) + lane]);
                se.x += ve.x; se.y += ve.y; se.z += ve.z; se.w += ve.w;
                sr.x += vr.x; sr.y += vr.y; sr.z += vr.z; sr.w += vr.w;
            }
        }
    }
    const float inv = 1.0f / (float)(cnt > 0 ? cnt : 1);
    float4 e = __ldg(&E4[(size_t)ents[gw] * (D / 4) + lane]);

    float* row = g_A1 + (size_t)gw * K1;
    float4 o0, o1, o2;
    o0.x = cvt_tf32(e.x);        o0.y = cvt_tf32(e.y);
    o0.z = cvt_tf32(e.z);        o0.w = cvt_tf32(e.w);
    o1.x = cvt_tf32(se.x * inv); o1.y = cvt_tf32(se.y * inv);
    o1.z = cvt_tf32(se.z * inv); o1.w = cvt_tf32(se.w * inv);
    o2.x = cvt_tf32(sr.x * inv); o2.y = cvt_tf32(sr.y * inv);
    o2.z = cvt_tf32(sr.z * inv); o2.w = cvt_tf32(sr.w * inv);
    *(float4*)(row + lane * 4)         = o0;
    *(float4*)(row + D + lane * 4)     = o1;
    *(float4*)(row + 2 * D + lane * 4) = o2;
}

// ---------------------------------------------------------------------------
__device__ __forceinline__ void cp16(void* smem, const void* gmem) {
    uint32_t s = (uint32_t)__cvta_generic_to_shared(smem);
    asm volatile("cp.async.cg.shared.global [%0], [%1], 16;" :: "r"(s), "l"(gmem));
}

// ---------------------------------------------------------------------------
// TF32 tensor-core GEMM, BK=32, 3-stage cp.async pipeline, ONE sync per tile.
// C[M,N] = relu(A[M,K] @ B[K,N] + bias[N]); inputs pre-rounded to tf32.
// Dynamic smem: [STAGES][BM*SAS] A | [STAGES][BK*SBS] B.
// ---------------------------------------------------------------------------
template <int BM, int BN, int WM, int WN, bool CVT_OUT>
__global__ void __launch_bounds__(WM * WN * 32)
mma_gemm_bias_relu(const float* __restrict__ A, const float* __restrict__ B,
                   const float* __restrict__ bias, float* __restrict__ C,
                   int M, int N, int K) {
    constexpr int BK      = 32;
    constexpr int STAGES  = 3;
    constexpr int THREADS = WM * WN * 32;
    constexpr int TMW     = BM / WM;
    constexpr int TNW     = BN / WN;
    constexpr int MF      = TMW / 16;
    constexpr int NF      = TNW / 8;
    constexpr int SAS     = BK + 4;          // 36: conflict-free frag loads
    constexpr int SBS     = BN + 8;          // mod 32 == 8: conflict-free
    constexpr int A_CH    = (BM * (BK / 4)) / THREADS;
    constexpr int B_CH    = (BK * (BN / 4)) / THREADS;
    constexpr int A_SZ    = BM * SAS;
    constexpr int B_SZ    = BK * SBS;

    extern __shared__ float smem[];
    float* sAb = smem;                        // STAGES * A_SZ
    float* sBb = smem + STAGES * A_SZ;        // STAGES * B_SZ

    const int tid  = threadIdx.x;
    const int wid  = tid >> 5;
    const int lane = tid & 31;
    const int grp  = lane >> 2;
    const int tg   = lane & 3;
    const int wm   = wid % WM;
    const int wn   = wid / WM;

    const int bx = blockIdx.x;
    const int by = blockIdx.y;

    const float* Ag = A + (size_t)by * BM * K;
    const float* Bg = B + (size_t)bx * BN;

    float acc[MF][NF][4];
    #pragma unroll
    for (int i = 0; i < MF; i++)
        #pragma unroll
        for (int j = 0; j < NF; j++)
            #pragma unroll
            for (int c = 0; c < 4; c++) acc[i][j][c] = 0.f;

    auto issue = [&](int t, int stg) {
        float* sA = sAb + stg * A_SZ;
        float* sB = sBb + stg * B_SZ;
        const float* At = Ag + t * BK;
        #pragma unroll
        for (int l = 0; l < A_CH; l++) {
            int idx = tid + l * THREADS;
            int row = idx >> 3;              // BK/4 = 8 chunks per row
            int c4  = idx & 7;
            cp16(&sA[row * SAS + c4 * 4], At + (size_t)row * K + c4 * 4);
        }
        const float* Bt = Bg + (size_t)t * BK * N;
        #pragma unroll
        for (int l = 0; l < B_CH; l++) {
            int idx = tid + l * THREADS;
            int row = idx / (BN / 4);
            int c4  = idx % (BN / 4);
            cp16(&sB[row * SBS + c4 * 4], Bt + (size_t)row * N + c4 * 4);
        }
    };

    const int ntiles = K / BK;

    #pragma unroll
    for (int s = 0; s < STAGES - 1; s++) {
        if (s < ntiles) issue(s, s);
        asm volatile("cp.async.commit_group;");
    }

    for (int t = 0; t < ntiles; t++) {
        asm volatile("cp.async.wait_group %0;" :: "n"(STAGES - 2));
        __syncthreads();
        // safe: every warp finished reading stage (t-1)%3 == (t+2)%3 before this sync
        const int nt = t + STAGES - 1;
        if (nt < ntiles) issue(nt, nt % STAGES);
        asm volatile("cp.async.commit_group;");

        const float* sA = sAb + (t % STAGES) * A_SZ;
        const float* sB = sBb + (t % STAGES) * B_SZ;
        #pragma unroll
        for (int ks = 0; ks < BK; ks += 8) {
            uint32_t af[MF][4];
            #pragma unroll
            for (int i = 0; i < MF; i++) {
                int rb = wm * TMW + i * 16 + grp;
                af[i][0] = __float_as_uint(sA[(rb + 0) * SAS + ks + tg]);
                af[i][1] = __float_as_uint(sA[(rb + 8) * SAS + ks + tg]);
                af[i][2] = __float_as_uint(sA[(rb + 0) * SAS + ks + tg + 4]);
                af[i][3] = __float_as_uint(sA[(rb + 8) * SAS + ks + tg + 4]);
            }
            uint32_t bf[NF][2];
            #pragma unroll
            for (int j = 0; j < NF; j++) {
                int cb = wn * TNW + j * 8 + grp;
                bf[j][0] = __float_as_uint(sB[(ks + tg) * SBS + cb]);
                bf[j][1] = __float_as_uint(sB[(ks + tg + 4) * SBS + cb]);
            }
            #pragma unroll
            for (int i = 0; i < MF; i++)
                #pragma unroll
                for (int j = 0; j < NF; j++) {
                    asm volatile(
                        "mma.sync.aligned.m16n8k8.row.col.f32.tf32.tf32.f32 "
                        "{%0,%1,%2,%3}, {%4,%5,%6,%7}, {%8,%9}, {%0,%1,%2,%3};"
                        : "+f"(acc[i][j][0]), "+f"(acc[i][j][1]),
                          "+f"(acc[i][j][2]), "+f"(acc[i][j][3])
                        : "r"(af[i][0]), "r"(af[i][1]), "r"(af[i][2]), "r"(af[i][3]),
                          "r"(bf[j][0]), "r"(bf[j][1]));
                }
        }
        // no trailing sync: next iteration's wait+sync guards stage reuse
    }

    // epilogue: bias + relu (+ optional tf32 rounding for the next GEMM)
    #pragma unroll
    for (int i = 0; i < MF; i++) {
        const int r0 = by * BM + wm * TMW + i * 16 + grp;
        #pragma unroll
        for (int j = 0; j < NF; j++) {
            const int c = bx * BN + wn * TNW + j * 8 + tg * 2;
            const float b0 = bias[c], b1 = bias[c + 1];
            float2 v0, v1;
            v0.x = fmaxf(acc[i][j][0] + b0, 0.f);
            v0.y = fmaxf(acc[i][j][1] + b1, 0.f);
            v1.x = fmaxf(acc[i][j][2] + b0, 0.f);
            v1.y = fmaxf(acc[i][j][3] + b1, 0.f);
            if (CVT_OUT) {
                v0.x = cvt_tf32(v0.x); v0.y = cvt_tf32(v0.y);
                v1.x = cvt_tf32(v1.x); v1.y = cvt_tf32(v1.y);
            }
            *(float2*)(C + (size_t)r0 * N + c)       = v0;
            *(float2*)(C + (size_t)(r0 + 8) * N + c) = v1;
        }
    }
}

// ---------------------------------------------------------------------------
extern "C" void kernel_launch(void* const* d_in, const int* in_sizes, int n_in,
                              void* d_out, int out_size) {
    const float* E    = (const float*)d_in[0];
    const float* R    = (const float*)d_in[1];
    const float* Wt   = (const float*)d_in[2];
    const float* bt   = (const float*)d_in[3];
    const float* Wn   = (const float*)d_in[4];
    const float* bn   = (const float*)d_in[5];
    const float* Wr   = (const float*)d_in[6];
    const float* br   = (const float*)d_in[7];
    const int*   ents = (const int*)d_in[8];
    const int*   nent = (const int*)d_in[9];
    const int*   nrel = (const int*)d_in[10];
    const int*   offs = (const int*)d_in[11];
    float* out = (float*)d_out;

    float *A1, *node, *W1, *Wr32, *b1;
    cudaGetSymbolAddress((void**)&A1,   g_A1);
    cudaGetSymbolAddress((void**)&node, g_node);
    cudaGetSymbolAddress((void**)&W1,   g_W1);
    cudaGetSymbolAddress((void**)&Wr32, g_Wr);
    cudaGetSymbolAddress((void**)&b1,   g_b1);

    // dynamic smem: 3 stages * (64*36 + 32*72) floats = 55296 bytes
    constexpr int SMEM = 3 * (64 * 36 + 32 * 72) * 4;
    cudaFuncSetAttribute(mma_gemm_bias_relu<64, 64, 2, 2, true>,
                         cudaFuncAttributeMaxDynamicSharedMemorySize, SMEM);
    cudaFuncSetAttribute(mma_gemm_bias_relu<64, 64, 2, 2, false>,
                         cudaFuncAttributeMaxDynamicSharedMemorySize, SMEM);

    // 0) weight prep
    prep_w<<<(K2 * H + 255) / 256, 256>>>(Wt, Wn, bt, bn, Wr);

    // 1) gather + segment mean -> A1 [8192, 384] (tf32)
    gather_mean<<<NODES / 8, 256>>>(E, R, ents, nent, nrel, offs);

    // 2) node = tf32(relu(A1 @ W1 + b1))   [8192, 256]   grid 4 x 128 = 512 CTAs
    mma_gemm_bias_relu<64, 64, 2, 2, true>
        <<<dim3(H / 64, NODES / 64), 128, SMEM>>>(A1, W1, b1, node, NODES, H, K1);

    // 3) out = relu(node.view(4096,512) @ Wr + br)        grid 4 x 64 = 256 CTAs
    mma_gemm_bias_relu<64, 64, 2, 2, false>
        <<<dim3(H / 64, BP / 64), 128, SMEM>>>(node, Wr32, br, out, BP, H, K2);
}